// round 2
// baseline (speedup 1.0000x reference)
#include <cuda_runtime.h>
#include <math.h>

// Problem constants
#define BQ   16
#define NQ   8192
#define SQ   2048
#define C1Q  128
#define C2Q  256
#define PQ   (BQ * NQ)      // 131072 total points
#define KX   384            // C1 + C2 (GEMM1 K)
#define M0Q  256            // layer0 out channels
#define M1Q  128            // layer1 out channels
#define BN_EPS 1e-5f

// ---------------- scratch (static device allocations; no cudaMalloc) --------
__device__ float g_w0f[M0Q * KX];        // BN-folded W0
__device__ float g_b0f[M0Q];
__device__ float g_w1f[M1Q * M0Q];       // BN-folded W1
__device__ float g_b1f[M1Q];
__device__ float g_f2t[BQ * SQ * C2Q];   // features_2 transposed: [b][s][c]
__device__ float g_x[KX * PQ];           // X matrix, channel-major: [c][p]
__device__ float g_y[M0Q * PQ];          // layer0 output: [m][p]
__device__ int   g_idx[PQ * 3];
__device__ float g_wt[PQ * 3];

// ---------------- BN fold ---------------------------------------------------
__global__ void fold0_kernel(const float* __restrict__ w, const float* __restrict__ b,
                             const float* __restrict__ g, const float* __restrict__ be,
                             const float* __restrict__ m, const float* __restrict__ v) {
    int o = blockIdx.x;                       // 0..255
    float s = g[o] * rsqrtf(v[o] + BN_EPS);
    int c = threadIdx.x;                      // 0..383
    g_w0f[o * KX + c] = w[o * KX + c] * s;
    if (c == 0) g_b0f[o] = (b[o] - m[o]) * s + be[o];
}

__global__ void fold1_kernel(const float* __restrict__ w, const float* __restrict__ b,
                             const float* __restrict__ g, const float* __restrict__ be,
                             const float* __restrict__ m, const float* __restrict__ v) {
    int o = blockIdx.x;                       // 0..127
    float s = g[o] * rsqrtf(v[o] + BN_EPS);
    int c = threadIdx.x;                      // 0..255
    g_w1f[o * M0Q + c] = w[o * M0Q + c] * s;
    if (c == 0) g_b1f[o] = (b[o] - m[o]) * s + be[o];
}

// ---------------- transpose features_2: (B,C2,S) -> (B,S,C2) ----------------
__global__ void transpose_f2_kernel(const float* __restrict__ f2) {
    __shared__ float tile[32][33];
    int b  = blockIdx.z;
    int s0 = blockIdx.x * 32;
    int c0 = blockIdx.y * 32;
    int s = s0 + threadIdx.x;
#pragma unroll
    for (int r = 0; r < 4; r++) {
        int c = c0 + threadIdx.y + r * 8;
        tile[threadIdx.y + r * 8][threadIdx.x] = f2[((size_t)b * C2Q + c) * SQ + s];
    }
    __syncthreads();
    int c = c0 + threadIdx.x;
#pragma unroll
    for (int r = 0; r < 4; r++) {
        int s2 = s0 + threadIdx.y + r * 8;
        g_f2t[((size_t)b * SQ + s2) * C2Q + c] = tile[threadIdx.x][threadIdx.y + r * 8];
    }
}

// ---------------- copy features_1 into X rows 0..127 (channel-major) --------
__global__ void copy_f1_kernel(const float* __restrict__ f1) {
    int bc = blockIdx.x;          // b*128 + c
    int b = bc >> 7;
    int c = bc & 127;
    const float4* src = (const float4*)(f1 + ((size_t)b * C1Q + c) * NQ);
    float4*       dst = (float4*)(g_x + (size_t)c * PQ + (size_t)b * NQ);
#pragma unroll
    for (int i = threadIdx.x; i < NQ / 4; i += 256)
        dst[i] = src[i];
}

// ---------------- 3-NN + inverse-distance weights ---------------------------
// Distance arithmetic deliberately matches the reference's operation order
// and rounding (no FMA contraction):
//   sq  = ((x*x + y*y) + z*z)                     [jnp.sum(c**2, axis=1)]
//   dot = ((x1*x2 + y1*y2) + z1*z2)               [einsum over d=3]
//   d   = (q2 + sq) - (dot + dot)                 [(A + B) - 2*C]
// This keeps our rounding error correlated with the reference's, so near-tie
// neighbor selections agree.
__global__ __launch_bounds__(256) void knn_kernel(const float* __restrict__ c1,
                                                  const float* __restrict__ c2) {
    __shared__ float sx[SQ], sy[SQ], sz[SQ], sq[SQ];
    int b = blockIdx.y;
    const float* cb = c2 + (size_t)b * 3 * SQ;
    for (int i = threadIdx.x; i < SQ; i += 256) {
        float x = cb[i], y = cb[SQ + i], z = cb[2 * SQ + i];
        sx[i] = x; sy[i] = y; sz[i] = z;
        sq[i] = __fadd_rn(__fadd_rn(__fmul_rn(x, x), __fmul_rn(y, y)), __fmul_rn(z, z));
    }
    __syncthreads();

    int n = blockIdx.x * 256 + threadIdx.x;
    const float* qb = c1 + (size_t)b * 3 * NQ;
    float x1 = qb[n], y1 = qb[NQ + n], z1 = qb[2 * NQ + n];
    float q2 = __fadd_rn(__fadd_rn(__fmul_rn(x1, x1), __fmul_rn(y1, y1)), __fmul_rn(z1, z1));

    float d0 = 1e30f, d1 = 1e30f, d2 = 1e30f;
    int   i0 = 0, i1 = 0, i2 = 0;
#pragma unroll 4
    for (int s = 0; s < SQ; s++) {
        float dot = __fadd_rn(__fadd_rn(__fmul_rn(x1, sx[s]), __fmul_rn(y1, sy[s])),
                              __fmul_rn(z1, sz[s]));
        float d = __fsub_rn(__fadd_rn(q2, sq[s]), __fadd_rn(dot, dot));
        if (d < d2) {
            if (d < d1) {
                d2 = d1; i2 = i1;
                if (d < d0) { d1 = d0; i1 = i0; d0 = d; i0 = s; }
                else        { d1 = d;  i1 = s; }
            } else { d2 = d; i2 = s; }
        }
    }
    d0 = fmaxf(d0, 1e-10f); d1 = fmaxf(d1, 1e-10f); d2 = fmaxf(d2, 1e-10f);
    float r0 = __fdiv_rn(1.0f, d0), r1 = __fdiv_rn(1.0f, d1), r2 = __fdiv_rn(1.0f, d2);
    float rs = __fadd_rn(__fadd_rn(r0, r1), r2);
    int p = b * NQ + n;
    g_idx[p * 3 + 0] = i0; g_idx[p * 3 + 1] = i1; g_idx[p * 3 + 2] = i2;
    g_wt[p * 3 + 0] = __fdiv_rn(r0, rs);
    g_wt[p * 3 + 1] = __fdiv_rn(r1, rs);
    g_wt[p * 3 + 2] = __fdiv_rn(r2, rs);
}

// ---------------- gather + interpolate into X rows 128..383 -----------------
// Reads f2t coalesced (c-contiguous per neighbor), transposes through SMEM,
// writes X channel-major (p-contiguous) coalesced. Interpolation uses plain
// mul/add rounding (matches reference's gathered*weight then sum).
__global__ __launch_bounds__(256) void gather_kernel() {
    __shared__ float tile[32][257];   // 257 pad: conflict-free c-major reads
    __shared__ int   sidx[32][3];
    __shared__ float swt[32][3];
    int p0 = blockIdx.x * 32;
    int t = threadIdx.x;
    if (t < 96) {
        int pl = t / 3, k = t - pl * 3;
        sidx[pl][k] = g_idx[(p0 + pl) * 3 + k];
        swt[pl][k]  = g_wt[(p0 + pl) * 3 + k];
    }
    __syncthreads();

    int warp = t >> 5, lane = t & 31;
#pragma unroll
    for (int it = 0; it < 4; it++) {
        int pl = warp * 4 + it;
        int p  = p0 + pl;
        int bb = p >> 13;
        const float* base = g_f2t + (size_t)bb * SQ * C2Q;
        const float* fa = base + (size_t)sidx[pl][0] * C2Q;
        const float* fb = base + (size_t)sidx[pl][1] * C2Q;
        const float* fc = base + (size_t)sidx[pl][2] * C2Q;
        float w0 = swt[pl][0], w1 = swt[pl][1], w2 = swt[pl][2];
#pragma unroll
        for (int q = 0; q < 2; q++) {
            int c = lane * 4 + q * 128;
            float4 a = *(const float4*)(fa + c);
            float4 b = *(const float4*)(fb + c);
            float4 cv = *(const float4*)(fc + c);
            tile[pl][c + 0] = __fadd_rn(__fadd_rn(__fmul_rn(a.x, w0), __fmul_rn(b.x, w1)), __fmul_rn(cv.x, w2));
            tile[pl][c + 1] = __fadd_rn(__fadd_rn(__fmul_rn(a.y, w0), __fmul_rn(b.y, w1)), __fmul_rn(cv.y, w2));
            tile[pl][c + 2] = __fadd_rn(__fadd_rn(__fmul_rn(a.z, w0), __fmul_rn(b.z, w1)), __fmul_rn(cv.z, w2));
            tile[pl][c + 3] = __fadd_rn(__fadd_rn(__fmul_rn(a.w, w0), __fmul_rn(b.w, w1)), __fmul_rn(cv.w, w2));
        }
    }
    __syncthreads();

    int pl2 = t & 31;
    int c0  = t >> 5;   // 0..7
    int pg  = p0 + pl2;
#pragma unroll
    for (int it = 0; it < 32; it++) {
        int c = c0 + it * 8;
        g_x[(size_t)(C1Q + c) * PQ + pg] = tile[pl2][c];
    }
}

// ---------------- tiled SGEMM: out[m][p] = relu(A[m][:]·X[:][p] + bias[m]) --
// A: MxK row-major (K-contig). X: KxP row-major (p-contig). 128x128 tile,
// BK=8, 256 threads, 8x8 microtile, register prefetch.
template <int KDIM, bool FINAL>
__device__ __forceinline__ void gemm_body(const float* __restrict__ A,
                                          const float* __restrict__ X,
                                          const float* __restrict__ bias,
                                          float* __restrict__ out) {
    __shared__ float As[8][128];
    __shared__ float Bs[8][128];
    const int tid = threadIdx.x;
    const int m0 = blockIdx.y * 128;
    const int p0 = blockIdx.x * 128;
    const int tx = tid & 15, ty = tid >> 4;

    const int arow  = tid >> 1;          // 0..127
    const int ak4   = (tid & 1) * 4;     // 0 or 4
    const int bk    = tid >> 5;          // 0..7
    const int blane = tid & 31;

    float4 aReg = *(const float4*)&A[(size_t)(m0 + arow) * KDIM + ak4];
    float4 bReg = *(const float4*)&X[(size_t)bk * PQ + p0 + blane * 4];

    float acc[8][8];
#pragma unroll
    for (int i = 0; i < 8; i++)
#pragma unroll
        for (int j = 0; j < 8; j++) acc[i][j] = 0.0f;

    for (int kc = 0; kc < KDIM; kc += 8) {
        __syncthreads();
        As[ak4 + 0][arow] = aReg.x;
        As[ak4 + 1][arow] = aReg.y;
        As[ak4 + 2][arow] = aReg.z;
        As[ak4 + 3][arow] = aReg.w;
        *(float4*)&Bs[bk][blane * 4] = bReg;
        __syncthreads();

        int kn = kc + 8;
        if (kn < KDIM) {
            aReg = *(const float4*)&A[(size_t)(m0 + arow) * KDIM + kn + ak4];
            bReg = *(const float4*)&X[(size_t)(kn + bk) * PQ + p0 + blane * 4];
        }
#pragma unroll
        for (int k = 0; k < 8; k++) {
            float a[8], b[8];
            *(float4*)&a[0] = *(float4*)&As[k][ty * 8];
            *(float4*)&a[4] = *(float4*)&As[k][ty * 8 + 4];
            *(float4*)&b[0] = *(float4*)&Bs[k][tx * 8];
            *(float4*)&b[4] = *(float4*)&Bs[k][tx * 8 + 4];
#pragma unroll
            for (int i = 0; i < 8; i++)
#pragma unroll
                for (int j = 0; j < 8; j++)
                    acc[i][j] = fmaf(a[i], b[j], acc[i][j]);
        }
    }

#pragma unroll
    for (int i = 0; i < 8; i++) {
        int m = m0 + ty * 8 + i;
        float bv = bias[m];
        float o[8];
#pragma unroll
        for (int j = 0; j < 8; j++) o[j] = fmaxf(acc[i][j] + bv, 0.0f);
        float* dst;
        if (FINAL) {
            int p = p0 + tx * 8;
            int bb = p >> 13;
            int n  = p & (NQ - 1);
            dst = out + ((size_t)bb * M1Q + m) * NQ + n;
        } else {
            dst = out + (size_t)m * PQ + p0 + tx * 8;
        }
        *(float4*)dst       = make_float4(o[0], o[1], o[2], o[3]);
        *(float4*)(dst + 4) = make_float4(o[4], o[5], o[6], o[7]);
    }
}

__global__ __launch_bounds__(256, 2) void gemm1_kernel() {
    gemm_body<KX, false>(g_w0f, g_x, g_b0f, g_y);
}

__global__ __launch_bounds__(256, 2) void gemm2_kernel(float* __restrict__ out) {
    gemm_body<M0Q, true>(g_w1f, g_y, g_b1f, out);
}

// ---------------- launch -----------------------------------------------------
extern "C" void kernel_launch(void* const* d_in, const int* in_sizes, int n_in,
                              void* d_out, int out_size) {
    const float* coords_1   = (const float*)d_in[0];
    const float* coords_2   = (const float*)d_in[1];
    const float* features_1 = (const float*)d_in[2];
    const float* features_2 = (const float*)d_in[3];
    const float* w0  = (const float*)d_in[4];
    const float* b0  = (const float*)d_in[5];
    const float* g0  = (const float*)d_in[6];
    const float* be0 = (const float*)d_in[7];
    const float* m0  = (const float*)d_in[8];
    const float* v0  = (const float*)d_in[9];
    const float* w1  = (const float*)d_in[10];
    const float* b1  = (const float*)d_in[11];
    const float* g1  = (const float*)d_in[12];
    const float* be1 = (const float*)d_in[13];
    const float* m1  = (const float*)d_in[14];
    const float* v1  = (const float*)d_in[15];
    float* out = (float*)d_out;

    fold0_kernel<<<M0Q, KX>>>(w0, b0, g0, be0, m0, v0);
    fold1_kernel<<<M1Q, M0Q>>>(w1, b1, g1, be1, m1, v1);
    transpose_f2_kernel<<<dim3(SQ / 32, C2Q / 32, BQ), dim3(32, 8)>>>(features_2);
    copy_f1_kernel<<<BQ * C1Q, 256>>>(features_1);
    knn_kernel<<<dim3(NQ / 256, BQ), 256>>>(coords_1, coords_2);
    gather_kernel<<<PQ / 32, 256>>>();
    gemm1_kernel<<<dim3(PQ / 128, M0Q / 128), 256>>>();
    gemm2_kernel<<<dim3(PQ / 128, M1Q / 128), 256>>>(out);
}

// round 3
// speedup vs baseline: 1.0679x; 1.0679x over previous
#include <cuda_runtime.h>
#include <math.h>

// Problem constants
#define BQ   16
#define NQ   8192
#define SQ   2048
#define C1Q  128
#define C2Q  256
#define PQ   (BQ * NQ)      // 131072 total points
#define KX   384            // C1 + C2 (GEMM1 K)
#define M0Q  256            // layer0 out channels
#define M1Q  128            // layer1 out channels
#define BN_EPS 1e-5f

// ---------------- scratch (static device allocations; no cudaMalloc) --------
__device__ float g_w0f[M0Q * KX];        // BN-folded W0
__device__ float g_b0f[M0Q];
__device__ float g_w1f[M1Q * M0Q];       // BN-folded W1
__device__ float g_b1f[M1Q];
__device__ float g_f2t[BQ * SQ * C2Q];   // features_2 transposed: [b][s][c]
__device__ float g_x[KX * PQ];           // X matrix, channel-major: [c][p]
__device__ float g_y[M0Q * PQ];          // layer0 output: [m][p]
__device__ int   g_idx[PQ * 3];
__device__ float g_wt[PQ * 3];

// ---------------- BN fold ---------------------------------------------------
__global__ void fold0_kernel(const float* __restrict__ w, const float* __restrict__ b,
                             const float* __restrict__ g, const float* __restrict__ be,
                             const float* __restrict__ m, const float* __restrict__ v) {
    int o = blockIdx.x;                       // 0..255
    float s = g[o] * rsqrtf(v[o] + BN_EPS);
    int c = threadIdx.x;                      // 0..383
    g_w0f[o * KX + c] = w[o * KX + c] * s;
    if (c == 0) g_b0f[o] = (b[o] - m[o]) * s + be[o];
}

__global__ void fold1_kernel(const float* __restrict__ w, const float* __restrict__ b,
                             const float* __restrict__ g, const float* __restrict__ be,
                             const float* __restrict__ m, const float* __restrict__ v) {
    int o = blockIdx.x;                       // 0..127
    float s = g[o] * rsqrtf(v[o] + BN_EPS);
    int c = threadIdx.x;                      // 0..255
    g_w1f[o * M0Q + c] = w[o * M0Q + c] * s;
    if (c == 0) g_b1f[o] = (b[o] - m[o]) * s + be[o];
}

// ---------------- transpose features_2: (B,C2,S) -> (B,S,C2) ----------------
__global__ void transpose_f2_kernel(const float* __restrict__ f2) {
    __shared__ float tile[32][33];
    int b  = blockIdx.z;
    int s0 = blockIdx.x * 32;
    int c0 = blockIdx.y * 32;
    int s = s0 + threadIdx.x;
#pragma unroll
    for (int r = 0; r < 4; r++) {
        int c = c0 + threadIdx.y + r * 8;
        tile[threadIdx.y + r * 8][threadIdx.x] = f2[((size_t)b * C2Q + c) * SQ + s];
    }
    __syncthreads();
    int c = c0 + threadIdx.x;
#pragma unroll
    for (int r = 0; r < 4; r++) {
        int s2 = s0 + threadIdx.y + r * 8;
        g_f2t[((size_t)b * SQ + s2) * C2Q + c] = tile[threadIdx.x][threadIdx.y + r * 8];
    }
}

// ---------------- copy features_1 into X rows 0..127 (channel-major) --------
__global__ void copy_f1_kernel(const float* __restrict__ f1) {
    int bc = blockIdx.x;          // b*128 + c
    int b = bc >> 7;
    int c = bc & 127;
    const float4* src = (const float4*)(f1 + ((size_t)b * C1Q + c) * NQ);
    float4*       dst = (float4*)(g_x + (size_t)c * PQ + (size_t)b * NQ);
#pragma unroll
    for (int i = threadIdx.x; i < NQ / 4; i += 256)
        dst[i] = src[i];
}

// ---------------- 3-NN + inverse-distance weights ---------------------------
// Distance arithmetic matches the reference's operation order and rounding
// (no FMA contraction). Candidate data packed as float4 (x,y,z,sq) in SMEM so
// the inner loop does a single LDS.128 per candidate (values bit-identical).
__global__ __launch_bounds__(256) void knn_kernel(const float* __restrict__ c1,
                                                  const float* __restrict__ c2) {
    __shared__ float4 sc[SQ];     // 32 KB
    int b = blockIdx.y;
    const float* cb = c2 + (size_t)b * 3 * SQ;
    for (int i = threadIdx.x; i < SQ; i += 256) {
        float x = cb[i], y = cb[SQ + i], z = cb[2 * SQ + i];
        float sq = __fadd_rn(__fadd_rn(__fmul_rn(x, x), __fmul_rn(y, y)), __fmul_rn(z, z));
        sc[i] = make_float4(x, y, z, sq);
    }
    __syncthreads();

    int n = blockIdx.x * 256 + threadIdx.x;
    const float* qb = c1 + (size_t)b * 3 * NQ;
    float x1 = qb[n], y1 = qb[NQ + n], z1 = qb[2 * NQ + n];
    float q2 = __fadd_rn(__fadd_rn(__fmul_rn(x1, x1), __fmul_rn(y1, y1)), __fmul_rn(z1, z1));

    float d0 = 1e30f, d1 = 1e30f, d2 = 1e30f;
    int   i0 = 0, i1 = 0, i2 = 0;
#pragma unroll 4
    for (int s = 0; s < SQ; s++) {
        float4 c = sc[s];
        float dot = __fadd_rn(__fadd_rn(__fmul_rn(x1, c.x), __fmul_rn(y1, c.y)),
                              __fmul_rn(z1, c.z));
        float d = __fsub_rn(__fadd_rn(q2, c.w), __fadd_rn(dot, dot));
        if (d < d2) {
            if (d < d1) {
                d2 = d1; i2 = i1;
                if (d < d0) { d1 = d0; i1 = i0; d0 = d; i0 = s; }
                else        { d1 = d;  i1 = s; }
            } else { d2 = d; i2 = s; }
        }
    }
    d0 = fmaxf(d0, 1e-10f); d1 = fmaxf(d1, 1e-10f); d2 = fmaxf(d2, 1e-10f);
    float r0 = __fdiv_rn(1.0f, d0), r1 = __fdiv_rn(1.0f, d1), r2 = __fdiv_rn(1.0f, d2);
    float rs = __fadd_rn(__fadd_rn(r0, r1), r2);
    int p = b * NQ + n;
    g_idx[p * 3 + 0] = i0; g_idx[p * 3 + 1] = i1; g_idx[p * 3 + 2] = i2;
    g_wt[p * 3 + 0] = __fdiv_rn(r0, rs);
    g_wt[p * 3 + 1] = __fdiv_rn(r1, rs);
    g_wt[p * 3 + 2] = __fdiv_rn(r2, rs);
}

// ---------------- gather + interpolate into X rows 128..383 -----------------
__global__ __launch_bounds__(256) void gather_kernel() {
    __shared__ float tile[32][257];   // 257 pad: conflict-free c-major reads
    __shared__ int   sidx[32][3];
    __shared__ float swt[32][3];
    int p0 = blockIdx.x * 32;
    int t = threadIdx.x;
    if (t < 96) {
        int pl = t / 3, k = t - pl * 3;
        sidx[pl][k] = g_idx[(p0 + pl) * 3 + k];
        swt[pl][k]  = g_wt[(p0 + pl) * 3 + k];
    }
    __syncthreads();

    int warp = t >> 5, lane = t & 31;
#pragma unroll
    for (int it = 0; it < 4; it++) {
        int pl = warp * 4 + it;
        int p  = p0 + pl;
        int bb = p >> 13;
        const float* base = g_f2t + (size_t)bb * SQ * C2Q;
        const float* fa = base + (size_t)sidx[pl][0] * C2Q;
        const float* fb = base + (size_t)sidx[pl][1] * C2Q;
        const float* fc = base + (size_t)sidx[pl][2] * C2Q;
        float w0 = swt[pl][0], w1 = swt[pl][1], w2 = swt[pl][2];
#pragma unroll
        for (int q = 0; q < 2; q++) {
            int c = lane * 4 + q * 128;
            float4 a = *(const float4*)(fa + c);
            float4 b = *(const float4*)(fb + c);
            float4 cv = *(const float4*)(fc + c);
            tile[pl][c + 0] = __fadd_rn(__fadd_rn(__fmul_rn(a.x, w0), __fmul_rn(b.x, w1)), __fmul_rn(cv.x, w2));
            tile[pl][c + 1] = __fadd_rn(__fadd_rn(__fmul_rn(a.y, w0), __fmul_rn(b.y, w1)), __fmul_rn(cv.y, w2));
            tile[pl][c + 2] = __fadd_rn(__fadd_rn(__fmul_rn(a.z, w0), __fmul_rn(b.z, w1)), __fmul_rn(cv.z, w2));
            tile[pl][c + 3] = __fadd_rn(__fadd_rn(__fmul_rn(a.w, w0), __fmul_rn(b.w, w1)), __fmul_rn(cv.w, w2));
        }
    }
    __syncthreads();

    int pl2 = t & 31;
    int c0  = t >> 5;   // 0..7
    int pg  = p0 + pl2;
#pragma unroll
    for (int it = 0; it < 32; it++) {
        int c = c0 + it * 8;
        g_x[(size_t)(C1Q + c) * PQ + pg] = tile[pl2][c];
    }
}

// ---------------- tiled SGEMM with packed f32x2 FMA --------------------------
// out[m][p] = relu(A[m][:]·X[:][p] + bias[m]).
// A: MxK row-major. X: KxP row-major (p-contig). 128x128 tile, BK=8,
// 256 threads, 8x8 microtile held as 8x4 packed f32x2 accumulators.
// B pairs come pre-packed from SMEM via double2 loads (pairs are adjacent);
// A broadcast pairs built with one mov.b64 per (i,k). Per-lane rounding and
// k-order are identical to the scalar FFMA version.
template <int KDIM, bool FINAL>
__device__ __forceinline__ void gemm_body(const float* __restrict__ A,
                                          const float* __restrict__ X,
                                          const float* __restrict__ bias,
                                          float* __restrict__ out) {
    __shared__ float As[8][128];
    __shared__ float Bs[8][128];
    const int tid = threadIdx.x;
    const int m0 = blockIdx.y * 128;
    const int p0 = blockIdx.x * 128;
    const int tx = tid & 15, ty = tid >> 4;

    const int arow  = tid >> 1;          // 0..127
    const int ak4   = (tid & 1) * 4;     // 0 or 4
    const int bk    = tid >> 5;          // 0..7
    const int blane = tid & 31;

    float4 aReg = *(const float4*)&A[(size_t)(m0 + arow) * KDIM + ak4];
    float4 bReg = *(const float4*)&X[(size_t)bk * PQ + p0 + blane * 4];

    unsigned long long acc[8][4];
#pragma unroll
    for (int i = 0; i < 8; i++)
#pragma unroll
        for (int j = 0; j < 4; j++) acc[i][j] = 0ull;

    for (int kc = 0; kc < KDIM; kc += 8) {
        __syncthreads();
        As[ak4 + 0][arow] = aReg.x;
        As[ak4 + 1][arow] = aReg.y;
        As[ak4 + 2][arow] = aReg.z;
        As[ak4 + 3][arow] = aReg.w;
        *(float4*)&Bs[bk][blane * 4] = bReg;
        __syncthreads();

        int kn = kc + 8;
        if (kn < KDIM) {
            aReg = *(const float4*)&A[(size_t)(m0 + arow) * KDIM + kn + ak4];
            bReg = *(const float4*)&X[(size_t)(kn + bk) * PQ + p0 + blane * 4];
        }
#pragma unroll
        for (int k = 0; k < 8; k++) {
            float a[8];
            *(float4*)&a[0] = *(float4*)&As[k][ty * 8];
            *(float4*)&a[4] = *(float4*)&As[k][ty * 8 + 4];
            // pairs (b[2j], b[2j+1]) are contiguous: load pre-packed as b64
            double2 bl0 = *(const double2*)&Bs[k][tx * 8];
            double2 bl1 = *(const double2*)&Bs[k][tx * 8 + 4];
            unsigned long long bp[4];
            bp[0] = __double_as_longlong(bl0.x);
            bp[1] = __double_as_longlong(bl0.y);
            bp[2] = __double_as_longlong(bl1.x);
            bp[3] = __double_as_longlong(bl1.y);
#pragma unroll
            for (int i = 0; i < 8; i++) {
                unsigned long long ap;
                asm("mov.b64 %0, {%1, %1};" : "=l"(ap) : "f"(a[i]));
#pragma unroll
                for (int j = 0; j < 4; j++)
                    asm("fma.rn.f32x2 %0, %1, %2, %0;"
                        : "+l"(acc[i][j]) : "l"(ap), "l"(bp[j]));
            }
        }
    }

#pragma unroll
    for (int i = 0; i < 8; i++) {
        int m = m0 + ty * 8 + i;
        float bv = bias[m];
        float o[8];
#pragma unroll
        for (int j = 0; j < 4; j++) {
            float lo = __uint_as_float((unsigned)(acc[i][j] & 0xffffffffull));
            float hi = __uint_as_float((unsigned)(acc[i][j] >> 32));
            o[2 * j]     = fmaxf(lo + bv, 0.0f);
            o[2 * j + 1] = fmaxf(hi + bv, 0.0f);
        }
        float* dst;
        if (FINAL) {
            int p = p0 + tx * 8;
            int bb = p >> 13;
            int n  = p & (NQ - 1);
            dst = out + ((size_t)bb * M1Q + m) * NQ + n;
        } else {
            dst = out + (size_t)m * PQ + p0 + tx * 8;
        }
        *(float4*)dst       = make_float4(o[0], o[1], o[2], o[3]);
        *(float4*)(dst + 4) = make_float4(o[4], o[5], o[6], o[7]);
    }
}

__global__ __launch_bounds__(256, 2) void gemm1_kernel() {
    gemm_body<KX, false>(g_w0f, g_x, g_b0f, g_y);
}

__global__ __launch_bounds__(256, 2) void gemm2_kernel(float* __restrict__ out) {
    gemm_body<M0Q, true>(g_w1f, g_y, g_b1f, out);
}

// ---------------- launch -----------------------------------------------------
extern "C" void kernel_launch(void* const* d_in, const int* in_sizes, int n_in,
                              void* d_out, int out_size) {
    const float* coords_1   = (const float*)d_in[0];
    const float* coords_2   = (const float*)d_in[1];
    const float* features_1 = (const float*)d_in[2];
    const float* features_2 = (const float*)d_in[3];
    const float* w0  = (const float*)d_in[4];
    const float* b0  = (const float*)d_in[5];
    const float* g0  = (const float*)d_in[6];
    const float* be0 = (const float*)d_in[7];
    const float* m0  = (const float*)d_in[8];
    const float* v0  = (const float*)d_in[9];
    const float* w1  = (const float*)d_in[10];
    const float* b1  = (const float*)d_in[11];
    const float* g1  = (const float*)d_in[12];
    const float* be1 = (const float*)d_in[13];
    const float* m1  = (const float*)d_in[14];
    const float* v1  = (const float*)d_in[15];
    float* out = (float*)d_out;

    fold0_kernel<<<M0Q, KX>>>(w0, b0, g0, be0, m0, v0);
    fold1_kernel<<<M1Q, M0Q>>>(w1, b1, g1, be1, m1, v1);
    transpose_f2_kernel<<<dim3(SQ / 32, C2Q / 32, BQ), dim3(32, 8)>>>(features_2);
    copy_f1_kernel<<<BQ * C1Q, 256>>>(features_1);
    knn_kernel<<<dim3(NQ / 256, BQ), 256>>>(coords_1, coords_2);
    gather_kernel<<<PQ / 32, 256>>>();
    gemm1_kernel<<<dim3(PQ / 128, M0Q / 128), 256>>>();
    gemm2_kernel<<<dim3(PQ / 128, M1Q / 128), 256>>>(out);
}